// round 4
// baseline (speedup 1.0000x reference)
#include <cuda_runtime.h>
#include <math_constants.h>
#include <cstdint>

#define NN 50000
#define NE 800000
#define ET (NE + NN)
#define DIM 128
#define NL 3
#define NG 64
#define NEG 0.2f

// ---- scratch ----
__device__ float g_h[NN * DIM];
__device__ float g_x[NN * DIM];
__device__ float g_ssrc[NN];
__device__ float g_sdst[NN];
__device__ int   g_deg[NN];
__device__ int   g_rowptr[NN + 1];
__device__ int   g_cursor[NN];
__device__ int   g_csrc[ET];

// ================= CSR build =================
__global__ __launch_bounds__(256) void zero_deg() {
    int i = blockIdx.x * blockDim.x + threadIdx.x;
    if (i < NN) g_deg[i] = 0;
}

__global__ __launch_bounds__(256) void count_deg(const int* __restrict__ ei) {
    int e = blockIdx.x * blockDim.x + threadIdx.x;
    if (e >= ET) return;
    int d = (e < NE) ? ei[NE + e] : (e - NE);
    atomicAdd(&g_deg[d], 1);
}

__global__ __launch_bounds__(1024) void scan_deg() {
    __shared__ int wsum[32];
    __shared__ int s_carry;
    int tid = threadIdx.x, lane = tid & 31, wid = tid >> 5;
    if (tid == 0) { s_carry = 0; g_rowptr[0] = 0; }
    __syncthreads();
    for (int base = 0; base < NN; base += 1024) {
        int i = base + tid;
        int v = (i < NN) ? g_deg[i] : 0;
        int x = v;
        #pragma unroll
        for (int off = 1; off < 32; off <<= 1) {
            int t = __shfl_up_sync(0xFFFFFFFFu, x, off);
            if (lane >= off) x += t;
        }
        if (lane == 31) wsum[wid] = x;
        __syncthreads();
        if (wid == 0) {
            int y = wsum[lane];
            #pragma unroll
            for (int off = 1; off < 32; off <<= 1) {
                int t = __shfl_up_sync(0xFFFFFFFFu, y, off);
                if (lane >= off) y += t;
            }
            wsum[lane] = y;
        }
        __syncthreads();
        int incl = x + (wid > 0 ? wsum[wid - 1] : 0) + s_carry;
        if (i < NN) { g_rowptr[i + 1] = incl; g_cursor[i] = incl - v; }
        __syncthreads();
        if (tid == 1023) s_carry = incl;
        __syncthreads();
    }
}

__global__ __launch_bounds__(256) void scatter_edges(const int* __restrict__ ei) {
    int e = blockIdx.x * blockDim.x + threadIdx.x;
    if (e >= ET) return;
    int s, d;
    if (e < NE) { s = ei[e]; d = ei[NE + e]; }
    else        { s = d = e - NE; }
    int pos = atomicAdd(&g_cursor[d], 1);
    g_csrc[pos] = s;
}

// ================= TF32x3 tensor-core GEMM + fused attention dots ==========
#define WS 136
#define GEMM_SMEM (2 * 128 * WS * 4 + 2 * 128 * 4)

__device__ __forceinline__ unsigned int f2tf32(float f) {
    unsigned int u;
    asm("cvt.rna.tf32.f32 %0, %1;" : "=r"(u) : "f"(f));
    return u;
}

__device__ __forceinline__ void mma_tf32(float* d, const unsigned int* a,
                                         unsigned int b0, unsigned int b1) {
    asm volatile("mma.sync.aligned.m16n8k8.row.col.f32.tf32.tf32.f32 "
                 "{%0,%1,%2,%3},{%4,%5,%6,%7},{%8,%9},{%0,%1,%2,%3};"
                 : "+f"(d[0]), "+f"(d[1]), "+f"(d[2]), "+f"(d[3])
                 : "r"(a[0]), "r"(a[1]), "r"(a[2]), "r"(a[3]), "r"(b0), "r"(b1));
}

__global__ __launch_bounds__(256) void gemm_tc(const float* __restrict__ Xin,
                                               const float* __restrict__ W,
                                               const float* __restrict__ asrc,
                                               const float* __restrict__ adst) {
    extern __shared__ unsigned int sm[];
    unsigned int* Whi = sm;
    unsigned int* Wlo = sm + 128 * WS;
    float* sdS = (float*)(sm + 2 * 128 * WS);
    float* sdD = sdS + 128;

    const float* X = Xin ? Xin : g_x;
    int tid = threadIdx.x;
    int lane = tid & 31, warp = tid >> 5;
    int wx = warp & 1, wy = warp >> 1;
    int g = lane >> 2, t = lane & 3;
    int rowbase = blockIdx.x * 128 + wy * 32;
    int colbase = wx * 64;

    // stage W as tf32 hi/lo
    for (int idx = tid; idx < 128 * 128; idx += 256) {
        int k = idx >> 7, n = idx & 127;
        float w = W[idx];
        unsigned int hi = f2tf32(w);
        unsigned int lo = f2tf32(w - __uint_as_float(hi));
        Whi[k * WS + n] = hi;
        Wlo[k * WS + n] = lo;
    }
    if (tid < 128) { sdS[tid] = 0.f; sdD[tid] = 0.f; }
    __syncthreads();

    float acc[2][8][4];
    #pragma unroll
    for (int mt = 0; mt < 2; mt++)
        #pragma unroll
        for (int nt = 0; nt < 8; nt++)
            #pragma unroll
            for (int i = 0; i < 4; i++) acc[mt][nt][i] = 0.f;

    for (int kt = 0; kt < 16; kt++) {
        int c0 = kt * 8 + t, c1 = c0 + 4;
        unsigned int ahi[2][4], alo[2][4];
        #pragma unroll
        for (int mt = 0; mt < 2; mt++) {
            int r0 = rowbase + mt * 16 + g, r1 = r0 + 8;
            bool v0 = r0 < NN, v1 = r1 < NN;
            float f0 = v0 ? X[r0 * DIM + c0] : 0.f;
            float f1 = v1 ? X[r1 * DIM + c0] : 0.f;
            float f2 = v0 ? X[r0 * DIM + c1] : 0.f;
            float f3 = v1 ? X[r1 * DIM + c1] : 0.f;
            ahi[mt][0] = f2tf32(f0); alo[mt][0] = f2tf32(f0 - __uint_as_float(ahi[mt][0]));
            ahi[mt][1] = f2tf32(f1); alo[mt][1] = f2tf32(f1 - __uint_as_float(ahi[mt][1]));
            ahi[mt][2] = f2tf32(f2); alo[mt][2] = f2tf32(f2 - __uint_as_float(ahi[mt][2]));
            ahi[mt][3] = f2tf32(f3); alo[mt][3] = f2tf32(f3 - __uint_as_float(ahi[mt][3]));
        }
        #pragma unroll
        for (int nt = 0; nt < 8; nt++) {
            int nc = colbase + nt * 8 + g;
            unsigned int bh0 = Whi[(kt * 8 + t) * WS + nc];
            unsigned int bh1 = Whi[(kt * 8 + t + 4) * WS + nc];
            unsigned int bl0 = Wlo[(kt * 8 + t) * WS + nc];
            unsigned int bl1 = Wlo[(kt * 8 + t + 4) * WS + nc];
            #pragma unroll
            for (int mt = 0; mt < 2; mt++) {
                mma_tf32(acc[mt][nt], ahi[mt], bh0, bh1);
                mma_tf32(acc[mt][nt], ahi[mt], bl0, bl1);
                mma_tf32(acc[mt][nt], alo[mt], bh0, bh1);
            }
        }
    }

    // epilogue: store h + fused attention dots
    float pS[2][2] = {{0.f, 0.f}, {0.f, 0.f}};
    float pD[2][2] = {{0.f, 0.f}, {0.f, 0.f}};
    #pragma unroll
    for (int nt = 0; nt < 8; nt++) {
        int c = colbase + nt * 8 + t * 2;
        float2 aS = *(const float2*)(asrc + c);
        float2 aD = *(const float2*)(adst + c);
        #pragma unroll
        for (int mt = 0; mt < 2; mt++) {
            int r0 = rowbase + mt * 16 + g, r1 = r0 + 8;
            if (r0 < NN)
                *(float2*)(&g_h[r0 * DIM + c]) = make_float2(acc[mt][nt][0], acc[mt][nt][1]);
            if (r1 < NN)
                *(float2*)(&g_h[r1 * DIM + c]) = make_float2(acc[mt][nt][2], acc[mt][nt][3]);
            pS[mt][0] += acc[mt][nt][0] * aS.x + acc[mt][nt][1] * aS.y;
            pS[mt][1] += acc[mt][nt][2] * aS.x + acc[mt][nt][3] * aS.y;
            pD[mt][0] += acc[mt][nt][0] * aD.x + acc[mt][nt][1] * aD.y;
            pD[mt][1] += acc[mt][nt][2] * aD.x + acc[mt][nt][3] * aD.y;
        }
    }
    #pragma unroll
    for (int o = 1; o <= 2; o <<= 1) {
        #pragma unroll
        for (int mt = 0; mt < 2; mt++) {
            #pragma unroll
            for (int hh = 0; hh < 2; hh++) {
                pS[mt][hh] += __shfl_xor_sync(0xFFFFFFFFu, pS[mt][hh], o);
                pD[mt][hh] += __shfl_xor_sync(0xFFFFFFFFu, pD[mt][hh], o);
            }
        }
    }
    if (t == 0) {
        #pragma unroll
        for (int mt = 0; mt < 2; mt++) {
            #pragma unroll
            for (int hh = 0; hh < 2; hh++) {
                int lr = wy * 32 + mt * 16 + hh * 8 + g;
                atomicAdd(&sdS[lr], pS[mt][hh]);
                atomicAdd(&sdD[lr], pD[mt][hh]);
            }
        }
    }
    __syncthreads();
    if (tid < 128) {
        int r = blockIdx.x * 128 + tid;
        if (r < NN) { g_ssrc[r] = sdS[tid]; g_sdst[r] = sdD[tid]; }
    }
}

__device__ __forceinline__ float leaky(float t) { return t > 0.f ? t : NEG * t; }

// ---- fused per-dst softmax + gather-aggregate + bias + relu (+ pool) ----
__global__ __launch_bounds__(256) void gat_agg(const float* __restrict__ bias,
                                               int do_pool,
                                               const int* __restrict__ batch,
                                               const float* __restrict__ Wf,
                                               float* __restrict__ y) {
    int d = (blockIdx.x * blockDim.x + threadIdx.x) >> 5;
    int lane = threadIdx.x & 31;
    if (d >= NN) return;

    int beg = g_rowptr[d], end = g_rowptr[d + 1];
    float sdst = g_sdst[d];

    float m = -CUDART_INF_F;
    for (int p = beg + lane; p < end; p += 32)
        m = fmaxf(m, leaky(g_ssrc[g_csrc[p]] + sdst));
    #pragma unroll
    for (int o = 16; o; o >>= 1) m = fmaxf(m, __shfl_xor_sync(0xFFFFFFFFu, m, o));

    float sum = 0.f;
    for (int p = beg + lane; p < end; p += 32)
        sum += __expf(leaky(g_ssrc[g_csrc[p]] + sdst) - m);
    #pragma unroll
    for (int o = 16; o; o >>= 1) sum += __shfl_xor_sync(0xFFFFFFFFu, sum, o);
    float inv = 1.f / (sum + 1e-16f);

    float4 acc = make_float4(0.f, 0.f, 0.f, 0.f);
    int p = beg;
    for (; p + 1 < end; p += 2) {
        int s0 = g_csrc[p], s1 = g_csrc[p + 1];
        float w0 = __expf(leaky(g_ssrc[s0] + sdst) - m) * inv;
        float w1 = __expf(leaky(g_ssrc[s1] + sdst) - m) * inv;
        float4 h0 = *(const float4*)(&g_h[s0 * DIM + 4 * lane]);
        float4 h1 = *(const float4*)(&g_h[s1 * DIM + 4 * lane]);
        acc.x += w0 * h0.x + w1 * h1.x;
        acc.y += w0 * h0.y + w1 * h1.y;
        acc.z += w0 * h0.z + w1 * h1.z;
        acc.w += w0 * h0.w + w1 * h1.w;
    }
    if (p < end) {
        int s0 = g_csrc[p];
        float w0 = __expf(leaky(g_ssrc[s0] + sdst) - m) * inv;
        float4 h0 = *(const float4*)(&g_h[s0 * DIM + 4 * lane]);
        acc.x += w0 * h0.x; acc.y += w0 * h0.y;
        acc.z += w0 * h0.z; acc.w += w0 * h0.w;
    }

    float4 b4 = *(const float4*)(&bias[4 * lane]);
    acc.x = fmaxf(acc.x + b4.x, 0.f);
    acc.y = fmaxf(acc.y + b4.y, 0.f);
    acc.z = fmaxf(acc.z + b4.z, 0.f);
    acc.w = fmaxf(acc.w + b4.w, 0.f);

    if (do_pool) {
        float4 w4 = *(const float4*)(&Wf[4 * lane]);
        float s = acc.x * w4.x + acc.y * w4.y + acc.z * w4.z + acc.w * w4.w;
        #pragma unroll
        for (int o = 16; o; o >>= 1) s += __shfl_xor_sync(0xFFFFFFFFu, s, o);
        if (lane == 0) atomicAdd(&y[batch[d]], s);
    } else {
        *(float4*)(&g_x[d * DIM + 4 * lane]) = acc;
    }
}

__global__ void init_y(const float* __restrict__ bf, float* __restrict__ y) {
    if (threadIdx.x < NG) y[threadIdx.x] = bf[0];
}

extern "C" void kernel_launch(void* const* d_in, const int* in_sizes, int n_in,
                              void* d_out, int out_size) {
    const float* x     = (const float*)d_in[0];
    const int*   ei    = (const int*)  d_in[1];
    const int*   batch = (const int*)  d_in[2];
    const float* Ws    = (const float*)d_in[3];
    const float* asrc  = (const float*)d_in[4];
    const float* adst  = (const float*)d_in[5];
    const float* bias  = (const float*)d_in[6];
    const float* Wf    = (const float*)d_in[7];
    const float* bf    = (const float*)d_in[8];
    float* y = (float*)d_out;

    const int EDGE_BLKS = (ET + 255) / 256;
    const int WARP_BLKS = (NN * 32 + 255) / 256;
    const int GEMM_BLKS = (NN + 127) / 128;

    cudaFuncSetAttribute(gemm_tc, cudaFuncAttributeMaxDynamicSharedMemorySize, GEMM_SMEM);

    zero_deg<<<(NN + 255) / 256, 256>>>();
    count_deg<<<EDGE_BLKS, 256>>>(ei);
    scan_deg<<<1, 1024>>>();
    scatter_edges<<<EDGE_BLKS, 256>>>(ei);
    init_y<<<1, 64>>>(bf, y);

    for (int l = 0; l < NL; l++) {
        gemm_tc<<<GEMM_BLKS, 256, GEMM_SMEM>>>(l == 0 ? x : nullptr, Ws + l * DIM * DIM,
                                               asrc + l * DIM, adst + l * DIM);
        gat_agg<<<WARP_BLKS, 256>>>(bias + l * DIM, l == NL - 1 ? 1 : 0, batch, Wf, y);
    }
}

// round 5
// speedup vs baseline: 1.0293x; 1.0293x over previous
#include <cuda_runtime.h>
#include <math_constants.h>
#include <cstdint>

#define NN 50000
#define NE 800000
#define ET (NE + NN)
#define DIM 128
#define NL 3
#define NG 64
#define NEG 0.2f

// ---- scratch ----
__device__ float g_h[NN * DIM];
__device__ float g_x[NN * DIM];
__device__ float g_ssrc[NN];
__device__ float g_sdst[NN];
__device__ int   g_deg[NN];
__device__ int   g_rowptr[NN + 1];
__device__ int   g_cursor[NN];
__device__ int   g_csrc[ET];
__device__ unsigned int g_Whi[NL * DIM * DIM];
__device__ unsigned int g_Wlo[NL * DIM * DIM];

// ================= CSR build =================
__global__ __launch_bounds__(256) void zero_deg() {
    int i = blockIdx.x * blockDim.x + threadIdx.x;
    if (i < NN) g_deg[i] = 0;
}

__global__ __launch_bounds__(256) void count_deg(const int* __restrict__ ei) {
    int e = blockIdx.x * blockDim.x + threadIdx.x;
    if (e >= ET) return;
    int d = (e < NE) ? ei[NE + e] : (e - NE);
    atomicAdd(&g_deg[d], 1);
}

__global__ __launch_bounds__(1024) void scan_deg() {
    __shared__ int wsum[32];
    __shared__ int s_carry;
    int tid = threadIdx.x, lane = tid & 31, wid = tid >> 5;
    if (tid == 0) { s_carry = 0; g_rowptr[0] = 0; }
    __syncthreads();
    for (int base = 0; base < NN; base += 1024) {
        int i = base + tid;
        int v = (i < NN) ? g_deg[i] : 0;
        int x = v;
        #pragma unroll
        for (int off = 1; off < 32; off <<= 1) {
            int t = __shfl_up_sync(0xFFFFFFFFu, x, off);
            if (lane >= off) x += t;
        }
        if (lane == 31) wsum[wid] = x;
        __syncthreads();
        if (wid == 0) {
            int y = wsum[lane];
            #pragma unroll
            for (int off = 1; off < 32; off <<= 1) {
                int t = __shfl_up_sync(0xFFFFFFFFu, y, off);
                if (lane >= off) y += t;
            }
            wsum[lane] = y;
        }
        __syncthreads();
        int incl = x + (wid > 0 ? wsum[wid - 1] : 0) + s_carry;
        if (i < NN) { g_rowptr[i + 1] = incl; g_cursor[i] = incl - v; }
        __syncthreads();
        if (tid == 1023) s_carry = incl;
        __syncthreads();
    }
}

__global__ __launch_bounds__(256) void scatter_edges(const int* __restrict__ ei) {
    int e = blockIdx.x * blockDim.x + threadIdx.x;
    if (e >= ET) return;
    int s, d;
    if (e < NE) { s = ei[e]; d = ei[NE + e]; }
    else        { s = d = e - NE; }
    int pos = atomicAdd(&g_cursor[d], 1);
    g_csrc[pos] = s;
}

// ================= W pre-conversion (once per launch) =================
__device__ __forceinline__ unsigned int f2tf32(float f) {
    unsigned int u;
    asm("cvt.rna.tf32.f32 %0, %1;" : "=r"(u) : "f"(f));
    return u;
}

__global__ __launch_bounds__(256) void conv_w(const float* __restrict__ Ws) {
    int i = blockIdx.x * blockDim.x + threadIdx.x;
    if (i >= NL * DIM * DIM) return;
    float w = Ws[i];
    unsigned int hi = f2tf32(w);
    g_Whi[i] = hi;
    g_Wlo[i] = f2tf32(w - __uint_as_float(hi));
}

// ================= TF32x3 GEMM + fused attention dots =================
// 128-row x 128-col tile, 256 threads (8 warps: wy 0..3, wx 0..1),
// two-phase smem reuse: phase1 Whi (Ahi*Bhi + Alo*Bhi), phase2 Wlo (Ahi*Blo).
#define WS 136
#define GEMM_SMEM (128 * WS * 4 + 2 * 128 * 4)

__device__ __forceinline__ void mma_tf32(float* d, const unsigned int* a,
                                         unsigned int b0, unsigned int b1) {
    asm volatile("mma.sync.aligned.m16n8k8.row.col.f32.tf32.tf32.f32 "
                 "{%0,%1,%2,%3},{%4,%5,%6,%7},{%8,%9},{%0,%1,%2,%3};"
                 : "+f"(d[0]), "+f"(d[1]), "+f"(d[2]), "+f"(d[3])
                 : "r"(a[0]), "r"(a[1]), "r"(a[2]), "r"(a[3]), "r"(b0), "r"(b1));
}

__global__ __launch_bounds__(256, 2) void gemm_tc(const float* __restrict__ Xin,
                                                  int layer,
                                                  const float* __restrict__ asrc,
                                                  const float* __restrict__ adst) {
    extern __shared__ unsigned int sm[];
    unsigned int* Wsh = sm;                       // 128 x WS
    float* sdS = (float*)(sm + 128 * WS);
    float* sdD = sdS + 128;

    const float* X = Xin ? Xin : g_x;
    int tid = threadIdx.x;
    int lane = tid & 31, warp = tid >> 5;
    int wx = warp & 1, wy = warp >> 1;
    int g = lane >> 2, t = lane & 3;
    int rowbase = blockIdx.x * 128 + wy * 32;
    int colbase = wx * 64;

    const float4* WhiG = (const float4*)(g_Whi + layer * DIM * DIM);
    const float4* WloG = (const float4*)(g_Wlo + layer * DIM * DIM);

    // stage Whi (float4 copy with WS padding)
    #pragma unroll
    for (int i = 0; i < 16; i++) {
        int idx = tid + 256 * i;                  // float4 index, 4096 total
        int k = idx >> 5, n4 = idx & 31;
        *(float4*)(&Wsh[k * WS + n4 * 4]) = WhiG[idx];
    }
    if (tid < 128) { sdS[tid] = 0.f; sdD[tid] = 0.f; }
    __syncthreads();

    float acc[2][8][4];
    #pragma unroll
    for (int mt = 0; mt < 2; mt++)
        #pragma unroll
        for (int nt = 0; nt < 8; nt++)
            #pragma unroll
            for (int i = 0; i < 4; i++) acc[mt][nt][i] = 0.f;

    // ---- phase 1: Ahi*Bhi + Alo*Bhi ----
    for (int kt = 0; kt < 16; kt++) {
        int c0 = kt * 8 + t, c1 = c0 + 4;
        unsigned int ahi[2][4], alo[2][4];
        #pragma unroll
        for (int mt = 0; mt < 2; mt++) {
            int r0 = rowbase + mt * 16 + g, r1 = r0 + 8;
            bool v0 = r0 < NN, v1 = r1 < NN;
            float f0 = v0 ? X[r0 * DIM + c0] : 0.f;
            float f1 = v1 ? X[r1 * DIM + c0] : 0.f;
            float f2 = v0 ? X[r0 * DIM + c1] : 0.f;
            float f3 = v1 ? X[r1 * DIM + c1] : 0.f;
            ahi[mt][0] = f2tf32(f0); alo[mt][0] = f2tf32(f0 - __uint_as_float(ahi[mt][0]));
            ahi[mt][1] = f2tf32(f1); alo[mt][1] = f2tf32(f1 - __uint_as_float(ahi[mt][1]));
            ahi[mt][2] = f2tf32(f2); alo[mt][2] = f2tf32(f2 - __uint_as_float(ahi[mt][2]));
            ahi[mt][3] = f2tf32(f3); alo[mt][3] = f2tf32(f3 - __uint_as_float(ahi[mt][3]));
        }
        #pragma unroll
        for (int nt = 0; nt < 8; nt++) {
            int nc = colbase + nt * 8 + g;
            unsigned int bh0 = Wsh[(kt * 8 + t) * WS + nc];
            unsigned int bh1 = Wsh[(kt * 8 + t + 4) * WS + nc];
            #pragma unroll
            for (int mt = 0; mt < 2; mt++) {
                mma_tf32(acc[mt][nt], ahi[mt], bh0, bh1);
                mma_tf32(acc[mt][nt], alo[mt], bh0, bh1);
            }
        }
    }

    // ---- phase 2: swap smem to Wlo, Ahi*Blo ----
    __syncthreads();
    #pragma unroll
    for (int i = 0; i < 16; i++) {
        int idx = tid + 256 * i;
        int k = idx >> 5, n4 = idx & 31;
        *(float4*)(&Wsh[k * WS + n4 * 4]) = WloG[idx];
    }
    __syncthreads();

    for (int kt = 0; kt < 16; kt++) {
        int c0 = kt * 8 + t, c1 = c0 + 4;
        unsigned int ahi[2][4];
        #pragma unroll
        for (int mt = 0; mt < 2; mt++) {
            int r0 = rowbase + mt * 16 + g, r1 = r0 + 8;
            bool v0 = r0 < NN, v1 = r1 < NN;
            ahi[mt][0] = f2tf32(v0 ? X[r0 * DIM + c0] : 0.f);
            ahi[mt][1] = f2tf32(v1 ? X[r1 * DIM + c0] : 0.f);
            ahi[mt][2] = f2tf32(v0 ? X[r0 * DIM + c1] : 0.f);
            ahi[mt][3] = f2tf32(v1 ? X[r1 * DIM + c1] : 0.f);
        }
        #pragma unroll
        for (int nt = 0; nt < 8; nt++) {
            int nc = colbase + nt * 8 + g;
            unsigned int bl0 = Wsh[(kt * 8 + t) * WS + nc];
            unsigned int bl1 = Wsh[(kt * 8 + t + 4) * WS + nc];
            #pragma unroll
            for (int mt = 0; mt < 2; mt++)
                mma_tf32(acc[mt][nt], ahi[mt], bl0, bl1);
        }
    }

    // ---- epilogue: store h + fused attention dots ----
    float pS[2][2] = {{0.f, 0.f}, {0.f, 0.f}};
    float pD[2][2] = {{0.f, 0.f}, {0.f, 0.f}};
    #pragma unroll
    for (int nt = 0; nt < 8; nt++) {
        int c = colbase + nt * 8 + t * 2;
        float2 aS = *(const float2*)(asrc + c);
        float2 aD = *(const float2*)(adst + c);
        #pragma unroll
        for (int mt = 0; mt < 2; mt++) {
            int r0 = rowbase + mt * 16 + g, r1 = r0 + 8;
            if (r0 < NN)
                *(float2*)(&g_h[r0 * DIM + c]) = make_float2(acc[mt][nt][0], acc[mt][nt][1]);
            if (r1 < NN)
                *(float2*)(&g_h[r1 * DIM + c]) = make_float2(acc[mt][nt][2], acc[mt][nt][3]);
            pS[mt][0] += acc[mt][nt][0] * aS.x + acc[mt][nt][1] * aS.y;
            pS[mt][1] += acc[mt][nt][2] * aS.x + acc[mt][nt][3] * aS.y;
            pD[mt][0] += acc[mt][nt][0] * aD.x + acc[mt][nt][1] * aD.y;
            pD[mt][1] += acc[mt][nt][2] * aD.x + acc[mt][nt][3] * aD.y;
        }
    }
    #pragma unroll
    for (int o = 1; o <= 2; o <<= 1) {
        #pragma unroll
        for (int mt = 0; mt < 2; mt++) {
            #pragma unroll
            for (int hh = 0; hh < 2; hh++) {
                pS[mt][hh] += __shfl_xor_sync(0xFFFFFFFFu, pS[mt][hh], o);
                pD[mt][hh] += __shfl_xor_sync(0xFFFFFFFFu, pD[mt][hh], o);
            }
        }
    }
    if (t == 0) {
        #pragma unroll
        for (int mt = 0; mt < 2; mt++) {
            #pragma unroll
            for (int hh = 0; hh < 2; hh++) {
                int lr = wy * 32 + mt * 16 + hh * 8 + g;
                atomicAdd(&sdS[lr], pS[mt][hh]);
                atomicAdd(&sdD[lr], pD[mt][hh]);
            }
        }
    }
    __syncthreads();
    if (tid < 128) {
        int r = blockIdx.x * 128 + tid;
        if (r < NN) { g_ssrc[r] = sdS[tid]; g_sdst[r] = sdD[tid]; }
    }
}

__device__ __forceinline__ float leaky(float t) { return t > 0.f ? t : NEG * t; }

// ---- fused per-dst softmax + gather-aggregate + bias + relu (+ pool) ----
__global__ __launch_bounds__(256) void gat_agg(const float* __restrict__ bias,
                                               int do_pool,
                                               const int* __restrict__ batch,
                                               const float* __restrict__ Wf,
                                               float* __restrict__ y) {
    int d = (blockIdx.x * blockDim.x + threadIdx.x) >> 5;
    int lane = threadIdx.x & 31;
    if (d >= NN) return;

    int beg = g_rowptr[d], end = g_rowptr[d + 1];
    float sdst = g_sdst[d];

    float m = -CUDART_INF_F;
    for (int p = beg + lane; p < end; p += 32)
        m = fmaxf(m, leaky(g_ssrc[g_csrc[p]] + sdst));
    #pragma unroll
    for (int o = 16; o; o >>= 1) m = fmaxf(m, __shfl_xor_sync(0xFFFFFFFFu, m, o));

    float sum = 0.f;
    for (int p = beg + lane; p < end; p += 32)
        sum += __expf(leaky(g_ssrc[g_csrc[p]] + sdst) - m);
    #pragma unroll
    for (int o = 16; o; o >>= 1) sum += __shfl_xor_sync(0xFFFFFFFFu, sum, o);
    float inv = 1.f / (sum + 1e-16f);

    float4 acc = make_float4(0.f, 0.f, 0.f, 0.f);
    int p = beg;
    for (; p + 1 < end; p += 2) {
        int s0 = g_csrc[p], s1 = g_csrc[p + 1];
        float w0 = __expf(leaky(g_ssrc[s0] + sdst) - m) * inv;
        float w1 = __expf(leaky(g_ssrc[s1] + sdst) - m) * inv;
        float4 h0 = *(const float4*)(&g_h[s0 * DIM + 4 * lane]);
        float4 h1 = *(const float4*)(&g_h[s1 * DIM + 4 * lane]);
        acc.x += w0 * h0.x + w1 * h1.x;
        acc.y += w0 * h0.y + w1 * h1.y;
        acc.z += w0 * h0.z + w1 * h1.z;
        acc.w += w0 * h0.w + w1 * h1.w;
    }
    if (p < end) {
        int s0 = g_csrc[p];
        float w0 = __expf(leaky(g_ssrc[s0] + sdst) - m) * inv;
        float4 h0 = *(const float4*)(&g_h[s0 * DIM + 4 * lane]);
        acc.x += w0 * h0.x; acc.y += w0 * h0.y;
        acc.z += w0 * h0.z; acc.w += w0 * h0.w;
    }

    float4 b4 = *(const float4*)(&bias[4 * lane]);
    acc.x = fmaxf(acc.x + b4.x, 0.f);
    acc.y = fmaxf(acc.y + b4.y, 0.f);
    acc.z = fmaxf(acc.z + b4.z, 0.f);
    acc.w = fmaxf(acc.w + b4.w, 0.f);

    if (do_pool) {
        float4 w4 = *(const float4*)(&Wf[4 * lane]);
        float s = acc.x * w4.x + acc.y * w4.y + acc.z * w4.z + acc.w * w4.w;
        #pragma unroll
        for (int o = 16; o; o >>= 1) s += __shfl_xor_sync(0xFFFFFFFFu, s, o);
        if (lane == 0) atomicAdd(&y[batch[d]], s);
    } else {
        *(float4*)(&g_x[d * DIM + 4 * lane]) = acc;
    }
}

__global__ void init_y(const float* __restrict__ bf, float* __restrict__ y) {
    if (threadIdx.x < NG) y[threadIdx.x] = bf[0];
}

extern "C" void kernel_launch(void* const* d_in, const int* in_sizes, int n_in,
                              void* d_out, int out_size) {
    const float* x     = (const float*)d_in[0];
    const int*   ei    = (const int*)  d_in[1];
    const int*   batch = (const int*)  d_in[2];
    const float* Ws    = (const float*)d_in[3];
    const float* asrc  = (const float*)d_in[4];
    const float* adst  = (const float*)d_in[5];
    const float* bias  = (const float*)d_in[6];
    const float* Wf    = (const float*)d_in[7];
    const float* bf    = (const float*)d_in[8];
    float* y = (float*)d_out;

    const int EDGE_BLKS = (ET + 255) / 256;
    const int WARP_BLKS = (NN * 32 + 255) / 256;
    const int GEMM_BLKS = (NN + 127) / 128;

    cudaFuncSetAttribute(gemm_tc, cudaFuncAttributeMaxDynamicSharedMemorySize, GEMM_SMEM);

    zero_deg<<<(NN + 255) / 256, 256>>>();
    count_deg<<<EDGE_BLKS, 256>>>(ei);
    conv_w<<<(NL * DIM * DIM + 255) / 256, 256>>>(Ws);
    scan_deg<<<1, 1024>>>();
    scatter_edges<<<EDGE_BLKS, 256>>>(ei);
    init_y<<<1, 64>>>(bf, y);

    for (int l = 0; l < NL; l++) {
        gemm_tc<<<GEMM_BLKS, 256, GEMM_SMEM>>>(l == 0 ? x : nullptr, l,
                                               asrc + l * DIM, adst + l * DIM);
        gat_agg<<<WARP_BLKS, 256>>>(bias + l * DIM, l == NL - 1 ? 1 : 0, batch, Wf, y);
    }
}

// round 6
// speedup vs baseline: 1.2528x; 1.2171x over previous
#include <cuda_runtime.h>
#include <math_constants.h>
#include <cstdint>

#define NN 50000
#define NE 800000
#define ET (NE + NN)
#define DIM 128
#define NL 3
#define NG 64
#define NEG 0.2f
#define SCAN_B ((NN + 1023) / 1024)   // 49

// ---- scratch ----
__device__ float g_h[NN * DIM];
__device__ float g_x[NN * DIM];
__device__ float g_ssrc[NN];
__device__ float g_sdst[NN];
__device__ int   g_deg[NN];
__device__ int   g_rowptr[NN + 1];
__device__ int   g_cursor[NN];
__device__ int   g_csrc[ET];
__device__ int   g_bsum[64];
__device__ int   g_boff[64];

// ================= CSR build =================
__global__ __launch_bounds__(256) void zero_deg() {
    int i = blockIdx.x * blockDim.x + threadIdx.x;
    if (i < NN) g_deg[i] = 0;
}

__global__ __launch_bounds__(256) void count_deg(const int* __restrict__ ei) {
    int e = blockIdx.x * blockDim.x + threadIdx.x;
    if (e >= ET) return;
    int d = (e < NE) ? ei[NE + e] : (e - NE);
    atomicAdd(&g_deg[d], 1);
}

// --- multi-block scan: local inclusive scan per 1024-chunk ---
__global__ __launch_bounds__(1024) void scan_local() {
    __shared__ int wsum[32];
    int tid = threadIdx.x, lane = tid & 31, wid = tid >> 5;
    int i = blockIdx.x * 1024 + tid;
    int v = (i < NN) ? g_deg[i] : 0;
    int x = v;
    #pragma unroll
    for (int off = 1; off < 32; off <<= 1) {
        int t = __shfl_up_sync(0xFFFFFFFFu, x, off);
        if (lane >= off) x += t;
    }
    if (lane == 31) wsum[wid] = x;
    __syncthreads();
    if (wid == 0) {
        int y = wsum[lane];
        #pragma unroll
        for (int off = 1; off < 32; off <<= 1) {
            int t = __shfl_up_sync(0xFFFFFFFFu, y, off);
            if (lane >= off) y += t;
        }
        wsum[lane] = y;
    }
    __syncthreads();
    int incl = x + (wid > 0 ? wsum[wid - 1] : 0);
    if (i < NN) { g_rowptr[i + 1] = incl; g_cursor[i] = incl - v; }
    if (tid == 1023) g_bsum[blockIdx.x] = incl;
}

// --- scan the 49 block sums (exclusive) ---
__global__ __launch_bounds__(64) void scan_bsum() {
    int tid = threadIdx.x, lane = tid & 31, wid = tid >> 5;
    __shared__ int w0sum;
    int v = (tid < SCAN_B) ? g_bsum[tid] : 0;
    int x = v;
    #pragma unroll
    for (int off = 1; off < 32; off <<= 1) {
        int t = __shfl_up_sync(0xFFFFFFFFu, x, off);
        if (lane >= off) x += t;
    }
    if (wid == 0 && lane == 31) w0sum = x;
    __syncthreads();
    int incl = x + (wid == 1 ? w0sum : 0);
    if (tid < SCAN_B) g_boff[tid] = incl - v;    // exclusive
}

// --- add block offsets ---
__global__ __launch_bounds__(1024) void scan_addoff() {
    int i = blockIdx.x * 1024 + threadIdx.x;
    if (i == 0) g_rowptr[0] = 0;
    if (i >= NN) return;
    int off = g_boff[blockIdx.x];
    g_rowptr[i + 1] += off;
    g_cursor[i] += off;
}

__global__ __launch_bounds__(256) void scatter_edges(const int* __restrict__ ei) {
    int e = blockIdx.x * blockDim.x + threadIdx.x;
    if (e >= ET) return;
    int s, d;
    if (e < NE) { s = ei[e]; d = ei[NE + e]; }
    else        { s = d = e - NE; }
    int pos = atomicAdd(&g_cursor[d], 1);
    g_csrc[pos] = s;
}

// ================= SIMT GEMM + fused attention dots =================
// 32 rows x 128 cols per block, 256 threads, thread = 4 rows x 4 cols.
// Warp = fixed ry (4 rows), all 32 col-groups -> dots via warp reduce.
__global__ __launch_bounds__(256) void gemm_kernel(const float* __restrict__ Xin,
                                                   const float* __restrict__ W,
                                                   const float* __restrict__ asrc,
                                                   const float* __restrict__ adst) {
    __shared__ float Wsh[64 * 128];
    __shared__ float xs[32][65];

    const float* X = Xin ? Xin : g_x;
    int row0 = blockIdx.x * 32;
    int cx = threadIdx.x & 31;
    int ry = threadIdx.x >> 5;

    float4 acc[4];
    #pragma unroll
    for (int r = 0; r < 4; r++) acc[r] = make_float4(0.f, 0.f, 0.f, 0.f);

    for (int c = 0; c < 2; c++) {
        const float4* Wg = (const float4*)(W + c * 64 * DIM);
        float4* Ws4 = (float4*)Wsh;
        #pragma unroll
        for (int i = 0; i < 8; i++) Ws4[threadIdx.x + 256 * i] = Wg[threadIdx.x + 256 * i];
        for (int idx = threadIdx.x; idx < 32 * 64; idx += 256) {
            int r = idx >> 6, k = idx & 63;
            int row = row0 + r;
            xs[r][k] = (row < NN) ? X[row * DIM + c * 64 + k] : 0.f;
        }
        __syncthreads();

        #pragma unroll 16
        for (int k = 0; k < 64; k++) {
            float4 w4 = *(const float4*)(&Wsh[k * DIM + 4 * cx]);
            #pragma unroll
            for (int r = 0; r < 4; r++) {
                float xv = xs[ry * 4 + r][k];
                acc[r].x += xv * w4.x;
                acc[r].y += xv * w4.y;
                acc[r].z += xv * w4.z;
                acc[r].w += xv * w4.w;
            }
        }
        __syncthreads();
    }

    // fused attention dots: warp owns rows ry*4..ry*4+3, all cols
    float4 aS = *(const float4*)(&asrc[4 * cx]);
    float4 aD = *(const float4*)(&adst[4 * cx]);
    float pS[4], pD[4];
    #pragma unroll
    for (int r = 0; r < 4; r++) {
        pS[r] = acc[r].x * aS.x + acc[r].y * aS.y + acc[r].z * aS.z + acc[r].w * aS.w;
        pD[r] = acc[r].x * aD.x + acc[r].y * aD.y + acc[r].z * aD.z + acc[r].w * aD.w;
        int row = row0 + ry * 4 + r;
        if (row < NN) *(float4*)(&g_h[row * DIM + 4 * cx]) = acc[r];
    }
    #pragma unroll
    for (int o = 16; o; o >>= 1) {
        #pragma unroll
        for (int r = 0; r < 4; r++) {
            pS[r] += __shfl_xor_sync(0xFFFFFFFFu, pS[r], o);
            pD[r] += __shfl_xor_sync(0xFFFFFFFFu, pD[r], o);
        }
    }
    if (cx == 0) {
        #pragma unroll
        for (int r = 0; r < 4; r++) {
            int row = row0 + ry * 4 + r;
            if (row < NN) { g_ssrc[row] = pS[r]; g_sdst[row] = pD[r]; }
        }
    }
}

__device__ __forceinline__ float leaky(float t) { return t > 0.f ? t : NEG * t; }

// ---- fused per-dst softmax + gather-aggregate + bias + relu (+ pool) ----
__global__ __launch_bounds__(256) void gat_agg(const float* __restrict__ bias,
                                               int do_pool,
                                               const int* __restrict__ batch,
                                               const float* __restrict__ Wf,
                                               float* __restrict__ y) {
    int d = (blockIdx.x * blockDim.x + threadIdx.x) >> 5;
    int lane = threadIdx.x & 31;
    if (d >= NN) return;

    int beg = g_rowptr[d], end = g_rowptr[d + 1];
    float sdst = g_sdst[d];

    float m = -CUDART_INF_F;
    for (int p = beg + lane; p < end; p += 32)
        m = fmaxf(m, leaky(g_ssrc[g_csrc[p]] + sdst));
    #pragma unroll
    for (int o = 16; o; o >>= 1) m = fmaxf(m, __shfl_xor_sync(0xFFFFFFFFu, m, o));

    float sum = 0.f;
    for (int p = beg + lane; p < end; p += 32)
        sum += __expf(leaky(g_ssrc[g_csrc[p]] + sdst) - m);
    #pragma unroll
    for (int o = 16; o; o >>= 1) sum += __shfl_xor_sync(0xFFFFFFFFu, sum, o);
    float inv = 1.f / (sum + 1e-16f);

    float4 acc = make_float4(0.f, 0.f, 0.f, 0.f);
    int p = beg;
    for (; p + 1 < end; p += 2) {
        int s0 = g_csrc[p], s1 = g_csrc[p + 1];
        float w0 = __expf(leaky(g_ssrc[s0] + sdst) - m) * inv;
        float w1 = __expf(leaky(g_ssrc[s1] + sdst) - m) * inv;
        float4 h0 = *(const float4*)(&g_h[s0 * DIM + 4 * lane]);
        float4 h1 = *(const float4*)(&g_h[s1 * DIM + 4 * lane]);
        acc.x += w0 * h0.x + w1 * h1.x;
        acc.y += w0 * h0.y + w1 * h1.y;
        acc.z += w0 * h0.z + w1 * h1.z;
        acc.w += w0 * h0.w + w1 * h1.w;
    }
    if (p < end) {
        int s0 = g_csrc[p];
        float w0 = __expf(leaky(g_ssrc[s0] + sdst) - m) * inv;
        float4 h0 = *(const float4*)(&g_h[s0 * DIM + 4 * lane]);
        acc.x += w0 * h0.x; acc.y += w0 * h0.y;
        acc.z += w0 * h0.z; acc.w += w0 * h0.w;
    }

    float4 b4 = *(const float4*)(&bias[4 * lane]);
    acc.x = fmaxf(acc.x + b4.x, 0.f);
    acc.y = fmaxf(acc.y + b4.y, 0.f);
    acc.z = fmaxf(acc.z + b4.z, 0.f);
    acc.w = fmaxf(acc.w + b4.w, 0.f);

    if (do_pool) {
        float4 w4 = *(const float4*)(&Wf[4 * lane]);
        float s = acc.x * w4.x + acc.y * w4.y + acc.z * w4.z + acc.w * w4.w;
        #pragma unroll
        for (int o = 16; o; o >>= 1) s += __shfl_xor_sync(0xFFFFFFFFu, s, o);
        if (lane == 0) atomicAdd(&y[batch[d]], s);
    } else {
        *(float4*)(&g_x[d * DIM + 4 * lane]) = acc;
    }
}

__global__ void init_y(const float* __restrict__ bf, float* __restrict__ y) {
    if (threadIdx.x < NG) y[threadIdx.x] = bf[0];
}

extern "C" void kernel_launch(void* const* d_in, const int* in_sizes, int n_in,
                              void* d_out, int out_size) {
    const float* x     = (const float*)d_in[0];
    const int*   ei    = (const int*)  d_in[1];
    const int*   batch = (const int*)  d_in[2];
    const float* Ws    = (const float*)d_in[3];
    const float* asrc  = (const float*)d_in[4];
    const float* adst  = (const float*)d_in[5];
    const float* bias  = (const float*)d_in[6];
    const float* Wf    = (const float*)d_in[7];
    const float* bf    = (const float*)d_in[8];
    float* y = (float*)d_out;

    const int EDGE_BLKS = (ET + 255) / 256;
    const int WARP_BLKS = (NN * 32 + 255) / 256;

    zero_deg<<<(NN + 255) / 256, 256>>>();
    count_deg<<<EDGE_BLKS, 256>>>(ei);
    scan_local<<<SCAN_B, 1024>>>();
    scan_bsum<<<1, 64>>>();
    scan_addoff<<<SCAN_B, 1024>>>();
    scatter_edges<<<EDGE_BLKS, 256>>>(ei);
    init_y<<<1, 64>>>(bf, y);

    for (int l = 0; l < NL; l++) {
        gemm_kernel<<<(NN + 31) / 32, 256>>>(l == 0 ? x : nullptr, Ws + l * DIM * DIM,
                                             asrc + l * DIM, adst + l * DIM);
        gat_agg<<<WARP_BLKS, 256>>>(bias + l * DIM, l == NL - 1 ? 1 : 0, batch, Wf, y);
    }
}

// round 7
// speedup vs baseline: 1.3866x; 1.1068x over previous
#include <cuda_runtime.h>
#include <math_constants.h>
#include <cstdint>

#define NN 50000
#define NE 800000
#define ET (NE + NN)
#define DIM 128
#define NL 3
#define NG 64
#define NEG 0.2f
#define SCAN_B ((NN + 1023) / 1024)   // 49

// ---- scratch ----
__device__ float g_h[NN * DIM];
__device__ float g_x[NN * DIM];
__device__ float g_ssrc[NN];
__device__ float g_sdst[NN];
__device__ int   g_deg[NN];
__device__ int   g_rowptr[NN + 1];
__device__ int   g_cursor[NN];
__device__ int   g_csrc[ET];
__device__ int   g_bsum[64];
__device__ int   g_boff[64];
__device__ unsigned int g_Whi[NL * DIM * DIM];
__device__ unsigned int g_Wlo[NL * DIM * DIM];

// ================= CSR build =================
__global__ __launch_bounds__(256) void zero_deg() {
    int i = blockIdx.x * blockDim.x + threadIdx.x;
    if (i < NN) g_deg[i] = 0;
}

__global__ __launch_bounds__(256) void count_deg(const int* __restrict__ ei) {
    int e = blockIdx.x * blockDim.x + threadIdx.x;
    if (e >= ET) return;
    int d = (e < NE) ? ei[NE + e] : (e - NE);
    atomicAdd(&g_deg[d], 1);
}

__global__ __launch_bounds__(1024) void scan_local() {
    __shared__ int wsum[32];
    int tid = threadIdx.x, lane = tid & 31, wid = tid >> 5;
    int i = blockIdx.x * 1024 + tid;
    int v = (i < NN) ? g_deg[i] : 0;
    int x = v;
    #pragma unroll
    for (int off = 1; off < 32; off <<= 1) {
        int t = __shfl_up_sync(0xFFFFFFFFu, x, off);
        if (lane >= off) x += t;
    }
    if (lane == 31) wsum[wid] = x;
    __syncthreads();
    if (wid == 0) {
        int y = wsum[lane];
        #pragma unroll
        for (int off = 1; off < 32; off <<= 1) {
            int t = __shfl_up_sync(0xFFFFFFFFu, y, off);
            if (lane >= off) y += t;
        }
        wsum[lane] = y;
    }
    __syncthreads();
    int incl = x + (wid > 0 ? wsum[wid - 1] : 0);
    if (i < NN) { g_rowptr[i + 1] = incl; g_cursor[i] = incl - v; }
    if (tid == 1023) g_bsum[blockIdx.x] = incl;
}

__global__ __launch_bounds__(64) void scan_bsum() {
    int tid = threadIdx.x, lane = tid & 31, wid = tid >> 5;
    __shared__ int w0sum;
    int v = (tid < SCAN_B) ? g_bsum[tid] : 0;
    int x = v;
    #pragma unroll
    for (int off = 1; off < 32; off <<= 1) {
        int t = __shfl_up_sync(0xFFFFFFFFu, x, off);
        if (lane >= off) x += t;
    }
    if (wid == 0 && lane == 31) w0sum = x;
    __syncthreads();
    int incl = x + (wid == 1 ? w0sum : 0);
    if (tid < SCAN_B) g_boff[tid] = incl - v;
}

__global__ __launch_bounds__(1024) void scan_addoff() {
    int i = blockIdx.x * 1024 + threadIdx.x;
    if (i == 0) g_rowptr[0] = 0;
    if (i >= NN) return;
    int off = g_boff[blockIdx.x];
    g_rowptr[i + 1] += off;
    g_cursor[i] += off;
}

__global__ __launch_bounds__(256) void scatter_edges(const int* __restrict__ ei) {
    int e = blockIdx.x * blockDim.x + threadIdx.x;
    if (e >= ET) return;
    int s, d;
    if (e < NE) { s = ei[e]; d = ei[NE + e]; }
    else        { s = d = e - NE; }
    int pos = atomicAdd(&g_cursor[d], 1);
    g_csrc[pos] = s;
}

// ================= W pre-conversion =================
__device__ __forceinline__ unsigned int f2tf32(float f) {
    unsigned int u;
    asm("cvt.rna.tf32.f32 %0, %1;" : "=r"(u) : "f"(f));
    return u;
}

__global__ __launch_bounds__(256) void conv_w(const float* __restrict__ Ws) {
    int i = blockIdx.x * blockDim.x + threadIdx.x;
    if (i >= NL * DIM * DIM) return;
    float w = Ws[i];
    unsigned int hi = f2tf32(w);
    g_Whi[i] = hi;
    g_Wlo[i] = f2tf32(w - __uint_as_float(hi));
}

__global__ __launch_bounds__(256) void zero_s() {
    int i = blockIdx.x * blockDim.x + threadIdx.x;
    if (i < NN) { g_ssrc[i] = 0.f; g_sdst[i] = 0.f; }
}

// ================= TF32x3 GEMM (smem-staged X) + partial dots =================
// Block = 128 rows x 64 cols. 8 warps: wy = warp>>1 (32 rows), wx = warp&1 (32 cols).
// Warp tile 32x32: mt 0..1 (m16), nt 0..3 (n8). K chunks of 32 staged in smem.
#define WPAD 68
#define XPAD 36
#define GEMM_SMEM ((2 * 128 * WPAD + 128 * XPAD) * 4)

__device__ __forceinline__ void mma_tf32(float* d, const unsigned int* a,
                                         unsigned int b0, unsigned int b1) {
    asm volatile("mma.sync.aligned.m16n8k8.row.col.f32.tf32.tf32.f32 "
                 "{%0,%1,%2,%3},{%4,%5,%6,%7},{%8,%9},{%0,%1,%2,%3};"
                 : "+f"(d[0]), "+f"(d[1]), "+f"(d[2]), "+f"(d[3])
                 : "r"(a[0]), "r"(a[1]), "r"(a[2]), "r"(a[3]), "r"(b0), "r"(b1));
}

__global__ __launch_bounds__(256, 2) void gemm_tc(const float* __restrict__ Xin,
                                                  int layer,
                                                  const float* __restrict__ asrc,
                                                  const float* __restrict__ adst) {
    extern __shared__ unsigned int sm[];
    unsigned int* Whi = sm;                         // 128 x WPAD
    unsigned int* Wlo = sm + 128 * WPAD;
    float* Xs = (float*)(sm + 2 * 128 * WPAD);      // 128 x XPAD

    const float* X = Xin ? Xin : g_x;
    int tid = threadIdx.x;
    int lane = tid & 31, warp = tid >> 5;
    int wx = warp & 1, wy = warp >> 1;
    int g = lane >> 2, t = lane & 3;
    int row0 = blockIdx.x * 128;
    int cb = blockIdx.y;                            // col block: cols cb*64..+63
    int colbase = cb * 64;

    // stage W slice (rows k=0..127, cols colbase..+63) hi+lo
    {
        const uint4* WhiG = (const uint4*)(g_Whi + layer * DIM * DIM);
        const uint4* WloG = (const uint4*)(g_Wlo + layer * DIM * DIM);
        #pragma unroll
        for (int i = 0; i < 8; i++) {
            int idx = tid + 256 * i;                // 2048 uint4
            int k = idx >> 4, q = idx & 15;
            int gsrc = k * (DIM / 4) + (colbase >> 2) + q;
            *(uint4*)(&Whi[k * WPAD + q * 4]) = WhiG[gsrc];
            *(uint4*)(&Wlo[k * WPAD + q * 4]) = WloG[gsrc];
        }
    }

    float acc[2][4][4];
    #pragma unroll
    for (int mt = 0; mt < 2; mt++)
        #pragma unroll
        for (int nt = 0; nt < 4; nt++)
            #pragma unroll
            for (int i = 0; i < 4; i++) acc[mt][nt][i] = 0.f;

    for (int kc = 0; kc < 4; kc++) {
        __syncthreads();
        // stage X chunk: 128 rows x 32 k (coalesced float4)
        #pragma unroll
        for (int i = 0; i < 4; i++) {
            int idx = tid + 256 * i;                // 1024 float4
            int r = idx >> 3, q = idx & 7;
            int grow = row0 + r;
            float4 v = (grow < NN)
                ? *(const float4*)(&X[grow * DIM + kc * 32 + q * 4])
                : make_float4(0.f, 0.f, 0.f, 0.f);
            *(float4*)(&Xs[r * XPAD + q * 4]) = v;
        }
        __syncthreads();

        #pragma unroll
        for (int kt = 0; kt < 4; kt++) {
            int k8 = kt * 8;
            unsigned int ahi[2][4], alo[2][4];
            #pragma unroll
            for (int mt = 0; mt < 2; mt++) {
                int lr0 = wy * 32 + mt * 16 + g, lr1 = lr0 + 8;
                float f0 = Xs[lr0 * XPAD + k8 + t];
                float f1 = Xs[lr1 * XPAD + k8 + t];
                float f2 = Xs[lr0 * XPAD + k8 + t + 4];
                float f3 = Xs[lr1 * XPAD + k8 + t + 4];
                ahi[mt][0] = f2tf32(f0); alo[mt][0] = f2tf32(f0 - __uint_as_float(ahi[mt][0]));
                ahi[mt][1] = f2tf32(f1); alo[mt][1] = f2tf32(f1 - __uint_as_float(ahi[mt][1]));
                ahi[mt][2] = f2tf32(f2); alo[mt][2] = f2tf32(f2 - __uint_as_float(ahi[mt][2]));
                ahi[mt][3] = f2tf32(f3); alo[mt][3] = f2tf32(f3 - __uint_as_float(ahi[mt][3]));
            }
            int krow = kc * 32 + k8;
            #pragma unroll
            for (int nt = 0; nt < 4; nt++) {
                int nc = wx * 32 + nt * 8 + g;
                unsigned int bh0 = Whi[(krow + t) * WPAD + nc];
                unsigned int bh1 = Whi[(krow + t + 4) * WPAD + nc];
                unsigned int bl0 = Wlo[(krow + t) * WPAD + nc];
                unsigned int bl1 = Wlo[(krow + t + 4) * WPAD + nc];
                #pragma unroll
                for (int mt = 0; mt < 2; mt++) {
                    mma_tf32(acc[mt][nt], ahi[mt], bh0, bh1);
                    mma_tf32(acc[mt][nt], alo[mt], bh0, bh1);
                    mma_tf32(acc[mt][nt], ahi[mt], bl0, bl1);
                }
            }
        }
    }

    // epilogue: store h + partial attention dots (atomic across 2 col-blocks)
    float pS[2][2] = {{0.f, 0.f}, {0.f, 0.f}};
    float pD[2][2] = {{0.f, 0.f}, {0.f, 0.f}};
    #pragma unroll
    for (int nt = 0; nt < 4; nt++) {
        int c = colbase + wx * 32 + nt * 8 + t * 2;
        float2 aS = *(const float2*)(asrc + c);
        float2 aD = *(const float2*)(adst + c);
        #pragma unroll
        for (int mt = 0; mt < 2; mt++) {
            int r0 = row0 + wy * 32 + mt * 16 + g, r1 = r0 + 8;
            if (r0 < NN)
                *(float2*)(&g_h[r0 * DIM + c]) = make_float2(acc[mt][nt][0], acc[mt][nt][1]);
            if (r1 < NN)
                *(float2*)(&g_h[r1 * DIM + c]) = make_float2(acc[mt][nt][2], acc[mt][nt][3]);
            pS[mt][0] += acc[mt][nt][0] * aS.x + acc[mt][nt][1] * aS.y;
            pS[mt][1] += acc[mt][nt][2] * aS.x + acc[mt][nt][3] * aS.y;
            pD[mt][0] += acc[mt][nt][0] * aD.x + acc[mt][nt][1] * aD.y;
            pD[mt][1] += acc[mt][nt][2] * aD.x + acc[mt][nt][3] * aD.y;
        }
    }
    #pragma unroll
    for (int o = 1; o <= 2; o <<= 1) {
        #pragma unroll
        for (int mt = 0; mt < 2; mt++) {
            #pragma unroll
            for (int hh = 0; hh < 2; hh++) {
                pS[mt][hh] += __shfl_xor_sync(0xFFFFFFFFu, pS[mt][hh], o);
                pD[mt][hh] += __shfl_xor_sync(0xFFFFFFFFu, pD[mt][hh], o);
            }
        }
    }
    if (t == 0) {
        #pragma unroll
        for (int mt = 0; mt < 2; mt++) {
            #pragma unroll
            for (int hh = 0; hh < 2; hh++) {
                int r = row0 + wy * 32 + mt * 16 + hh * 8 + g;
                if (r < NN) {
                    atomicAdd(&g_ssrc[r], pS[mt][hh]);
                    atomicAdd(&g_sdst[r], pD[mt][hh]);
                }
            }
        }
    }
}

__device__ __forceinline__ float leaky(float t) { return t > 0.f ? t : NEG * t; }

// ---- fused per-dst softmax + gather-aggregate + bias + relu (+ pool) ----
__global__ __launch_bounds__(256) void gat_agg(const float* __restrict__ bias,
                                               int do_pool,
                                               const int* __restrict__ batch,
                                               const float* __restrict__ Wf,
                                               float* __restrict__ y) {
    int d = (blockIdx.x * blockDim.x + threadIdx.x) >> 5;
    int lane = threadIdx.x & 31;
    if (d >= NN) return;

    int beg = g_rowptr[d], end = g_rowptr[d + 1];
    float sdst = g_sdst[d];

    float m = -CUDART_INF_F;
    for (int p = beg + lane; p < end; p += 32)
        m = fmaxf(m, leaky(g_ssrc[g_csrc[p]] + sdst));
    #pragma unroll
    for (int o = 16; o; o >>= 1) m = fmaxf(m, __shfl_xor_sync(0xFFFFFFFFu, m, o));

    float sum = 0.f;
    for (int p = beg + lane; p < end; p += 32)
        sum += __expf(leaky(g_ssrc[g_csrc[p]] + sdst) - m);
    #pragma unroll
    for (int o = 16; o; o >>= 1) sum += __shfl_xor_sync(0xFFFFFFFFu, sum, o);
    float inv = 1.f / (sum + 1e-16f);

    float4 acc = make_float4(0.f, 0.f, 0.f, 0.f);
    int p = beg;
    for (; p + 1 < end; p += 2) {
        int s0 = g_csrc[p], s1 = g_csrc[p + 1];
        float w0 = __expf(leaky(g_ssrc[s0] + sdst) - m) * inv;
        float w1 = __expf(leaky(g_ssrc[s1] + sdst) - m) * inv;
        float4 h0 = *(const float4*)(&g_h[s0 * DIM + 4 * lane]);
        float4 h1 = *(const float4*)(&g_h[s1 * DIM + 4 * lane]);
        acc.x += w0 * h0.x + w1 * h1.x;
        acc.y += w0 * h0.y + w1 * h1.y;
        acc.z += w0 * h0.z + w1 * h1.z;
        acc.w += w0 * h0.w + w1 * h1.w;
    }
    if (p < end) {
        int s0 = g_csrc[p];
        float w0 = __expf(leaky(g_ssrc[s0] + sdst) - m) * inv;
        float4 h0 = *(const float4*)(&g_h[s0 * DIM + 4 * lane]);
        acc.x += w0 * h0.x; acc.y += w0 * h0.y;
        acc.z += w0 * h0.z; acc.w += w0 * h0.w;
    }

    float4 b4 = *(const float4*)(&bias[4 * lane]);
    acc.x = fmaxf(acc.x + b4.x, 0.f);
    acc.y = fmaxf(acc.y + b4.y, 0.f);
    acc.z = fmaxf(acc.z + b4.z, 0.f);
    acc.w = fmaxf(acc.w + b4.w, 0.f);

    if (do_pool) {
        float4 w4 = *(const float4*)(&Wf[4 * lane]);
        float s = acc.x * w4.x + acc.y * w4.y + acc.z * w4.z + acc.w * w4.w;
        #pragma unroll
        for (int o = 16; o; o >>= 1) s += __shfl_xor_sync(0xFFFFFFFFu, s, o);
        if (lane == 0) atomicAdd(&y[batch[d]], s);
    } else {
        *(float4*)(&g_x[d * DIM + 4 * lane]) = acc;
    }
}

__global__ void init_y(const float* __restrict__ bf, float* __restrict__ y) {
    if (threadIdx.x < NG) y[threadIdx.x] = bf[0];
}

extern "C" void kernel_launch(void* const* d_in, const int* in_sizes, int n_in,
                              void* d_out, int out_size) {
    const float* x     = (const float*)d_in[0];
    const int*   ei    = (const int*)  d_in[1];
    const int*   batch = (const int*)  d_in[2];
    const float* Ws    = (const float*)d_in[3];
    const float* asrc  = (const float*)d_in[4];
    const float* adst  = (const float*)d_in[5];
    const float* bias  = (const float*)d_in[6];
    const float* Wf    = (const float*)d_in[7];
    const float* bf    = (const float*)d_in[8];
    float* y = (float*)d_out;

    const int EDGE_BLKS = (ET + 255) / 256;
    const int WARP_BLKS = (NN * 32 + 255) / 256;
    const dim3 GEMM_GRID((NN + 127) / 128, 2);

    cudaFuncSetAttribute(gemm_tc, cudaFuncAttributeMaxDynamicSharedMemorySize, GEMM_SMEM);

    zero_deg<<<(NN + 255) / 256, 256>>>();
    count_deg<<<EDGE_BLKS, 256>>>(ei);
    conv_w<<<(NL * DIM * DIM + 255) / 256, 256>>>(Ws);
    scan_local<<<SCAN_B, 1024>>>();
    scan_bsum<<<1, 64>>>();
    scan_addoff<<<SCAN_B, 1024>>>();
    scatter_edges<<<EDGE_BLKS, 256>>>(ei);
    init_y<<<1, 64>>>(bf, y);

    for (int l = 0; l < NL; l++) {
        zero_s<<<(NN + 255) / 256, 256>>>();
        gemm_tc<<<GEMM_GRID, 256, GEMM_SMEM>>>(l == 0 ? x : nullptr, l,
                                               asrc + l * DIM, adst + l * DIM);
        gat_agg<<<WARP_BLKS, 256>>>(bias + l * DIM, l == NL - 1 ? 1 : 0, batch, Wf, y);
    }
}

// round 8
// speedup vs baseline: 1.4472x; 1.0437x over previous
#include <cuda_runtime.h>
#include <math_constants.h>
#include <cstdint>

#define NN 50000
#define NE 800000
#define ET (NE + NN)
#define DIM 128
#define NL 3
#define NG 64
#define NEG 0.2f
#define SCAN_B ((NN + 1023) / 1024)   // 49
#define FULLM 0xFFFFFFFFu

// ---- scratch ----
__device__ float g_h[NN * DIM];
__device__ float g_x[NN * DIM];
__device__ float g_ssrc[NN];
__device__ float g_sdst[NN];
__device__ int   g_deg[NN];
__device__ int   g_rowptr[NN + 1];
__device__ int   g_cursor[NN];
__device__ int   g_csrc[ET];
__device__ int   g_bsum[64];
__device__ int   g_boff[64];
__device__ unsigned int g_Whi[NL * DIM * DIM];
__device__ unsigned int g_Wlo[NL * DIM * DIM];

// ================= CSR build =================
__global__ __launch_bounds__(256) void zero_deg() {
    int i = blockIdx.x * blockDim.x + threadIdx.x;
    if (i < NN) g_deg[i] = 0;
}

__global__ __launch_bounds__(256) void count_deg(const int* __restrict__ ei) {
    int e = blockIdx.x * blockDim.x + threadIdx.x;
    if (e >= ET) return;
    int d = (e < NE) ? ei[NE + e] : (e - NE);
    atomicAdd(&g_deg[d], 1);
}

__global__ __launch_bounds__(1024) void scan_local() {
    __shared__ int wsum[32];
    int tid = threadIdx.x, lane = tid & 31, wid = tid >> 5;
    int i = blockIdx.x * 1024 + tid;
    int v = (i < NN) ? g_deg[i] : 0;
    int x = v;
    #pragma unroll
    for (int off = 1; off < 32; off <<= 1) {
        int t = __shfl_up_sync(FULLM, x, off);
        if (lane >= off) x += t;
    }
    if (lane == 31) wsum[wid] = x;
    __syncthreads();
    if (wid == 0) {
        int y = wsum[lane];
        #pragma unroll
        for (int off = 1; off < 32; off <<= 1) {
            int t = __shfl_up_sync(FULLM, y, off);
            if (lane >= off) y += t;
        }
        wsum[lane] = y;
    }
    __syncthreads();
    int incl = x + (wid > 0 ? wsum[wid - 1] : 0);
    if (i < NN) { g_rowptr[i + 1] = incl; g_cursor[i] = incl - v; }
    if (tid == 1023) g_bsum[blockIdx.x] = incl;
}

__global__ __launch_bounds__(64) void scan_bsum() {
    int tid = threadIdx.x, lane = tid & 31, wid = tid >> 5;
    __shared__ int w0sum;
    int v = (tid < SCAN_B) ? g_bsum[tid] : 0;
    int x = v;
    #pragma unroll
    for (int off = 1; off < 32; off <<= 1) {
        int t = __shfl_up_sync(FULLM, x, off);
        if (lane >= off) x += t;
    }
    if (wid == 0 && lane == 31) w0sum = x;
    __syncthreads();
    int incl = x + (wid == 1 ? w0sum : 0);
    if (tid < SCAN_B) g_boff[tid] = incl - v;
}

__global__ __launch_bounds__(1024) void scan_addoff() {
    int i = blockIdx.x * 1024 + threadIdx.x;
    if (i == 0) g_rowptr[0] = 0;
    if (i >= NN) return;
    int off = g_boff[blockIdx.x];
    g_rowptr[i + 1] += off;
    g_cursor[i] += off;
}

__global__ __launch_bounds__(256) void scatter_edges(const int* __restrict__ ei) {
    int e = blockIdx.x * blockDim.x + threadIdx.x;
    if (e >= ET) return;
    int s, d;
    if (e < NE) { s = ei[e]; d = ei[NE + e]; }
    else        { s = d = e - NE; }
    int pos = atomicAdd(&g_cursor[d], 1);
    g_csrc[pos] = s;
}

// ================= W pre-conversion =================
__device__ __forceinline__ unsigned int f2tf32(float f) {
    unsigned int u;
    asm("cvt.rna.tf32.f32 %0, %1;" : "=r"(u) : "f"(f));
    return u;
}

__global__ __launch_bounds__(256) void conv_w(const float* __restrict__ Ws) {
    int i = blockIdx.x * blockDim.x + threadIdx.x;
    if (i >= NL * DIM * DIM) return;
    float w = Ws[i];
    unsigned int hi = f2tf32(w);
    g_Whi[i] = hi;
    g_Wlo[i] = f2tf32(w - __uint_as_float(hi));
}

// ================= TF32x3 GEMM (128x128 block) + fused dots =================
// 8 warps: wy = warp>>1 (32-row strip), wx = warp&1 (64-col strip).
// Warp tile 32x64: mt 0..1, nt 0..7. K chunks of 32: stage W chunk hi/lo + X chunk.
#define WP 136
#define XP 36
#define GEMM_SMEM ((2 * 32 * WP + 128 * XP + 2 * 128) * 4)

__device__ __forceinline__ void mma_tf32(float* d, const unsigned int* a,
                                         unsigned int b0, unsigned int b1) {
    asm volatile("mma.sync.aligned.m16n8k8.row.col.f32.tf32.tf32.f32 "
                 "{%0,%1,%2,%3},{%4,%5,%6,%7},{%8,%9},{%0,%1,%2,%3};"
                 : "+f"(d[0]), "+f"(d[1]), "+f"(d[2]), "+f"(d[3])
                 : "r"(a[0]), "r"(a[1]), "r"(a[2]), "r"(a[3]), "r"(b0), "r"(b1));
}

__global__ __launch_bounds__(256, 2) void gemm_tc(const float* __restrict__ Xin,
                                                  int layer,
                                                  const float* __restrict__ asrc,
                                                  const float* __restrict__ adst) {
    extern __shared__ unsigned int sm[];
    unsigned int* Whi = sm;                     // 32 x WP
    unsigned int* Wlo = sm + 32 * WP;
    float* Xs  = (float*)(sm + 64 * WP);        // 128 x XP
    float* sdS = Xs + 128 * XP;
    float* sdD = sdS + 128;

    const float* X = Xin ? Xin : g_x;
    int tid = threadIdx.x;
    int lane = tid & 31, warp = tid >> 5;
    int wx = warp & 1, wy = warp >> 1;
    int g = lane >> 2, t = lane & 3;
    int row0 = blockIdx.x * 128;

    const uint4* WhiG = (const uint4*)(g_Whi + layer * DIM * DIM);
    const uint4* WloG = (const uint4*)(g_Wlo + layer * DIM * DIM);

    if (tid < 128) { sdS[tid] = 0.f; sdD[tid] = 0.f; }

    float acc[2][8][4];
    #pragma unroll
    for (int mt = 0; mt < 2; mt++)
        #pragma unroll
        for (int nt = 0; nt < 8; nt++)
            #pragma unroll
            for (int i = 0; i < 4; i++) acc[mt][nt][i] = 0.f;

    for (int kc = 0; kc < 4; kc++) {
        __syncthreads();
        // stage W chunk: k rows kc*32..+31, 128 cols (1024 uint4 each for hi/lo)
        #pragma unroll
        for (int i = 0; i < 4; i++) {
            int idx = tid + 256 * i;
            int k = idx >> 5, q = idx & 31;
            int gsrc = (kc * 32 + k) * 32 + q;
            *(uint4*)(&Whi[k * WP + q * 4]) = WhiG[gsrc];
            *(uint4*)(&Wlo[k * WP + q * 4]) = WloG[gsrc];
        }
        // stage X chunk: 128 rows x 32 k (1024 float4)
        #pragma unroll
        for (int i = 0; i < 4; i++) {
            int idx = tid + 256 * i;
            int r = idx >> 3, q = idx & 7;
            int grow = row0 + r;
            float4 v = (grow < NN)
                ? *(const float4*)(&X[grow * DIM + kc * 32 + q * 4])
                : make_float4(0.f, 0.f, 0.f, 0.f);
            *(float4*)(&Xs[r * XP + q * 4]) = v;
        }
        __syncthreads();

        #pragma unroll
        for (int kt = 0; kt < 4; kt++) {
            int k8 = kt * 8;
            unsigned int ahi[2][4], alo[2][4];
            #pragma unroll
            for (int mt = 0; mt < 2; mt++) {
                int lr0 = wy * 32 + mt * 16 + g, lr1 = lr0 + 8;
                float f0 = Xs[lr0 * XP + k8 + t];
                float f1 = Xs[lr1 * XP + k8 + t];
                float f2 = Xs[lr0 * XP + k8 + t + 4];
                float f3 = Xs[lr1 * XP + k8 + t + 4];
                ahi[mt][0] = f2tf32(f0); alo[mt][0] = f2tf32(f0 - __uint_as_float(ahi[mt][0]));
                ahi[mt][1] = f2tf32(f1); alo[mt][1] = f2tf32(f1 - __uint_as_float(ahi[mt][1]));
                ahi[mt][2] = f2tf32(f2); alo[mt][2] = f2tf32(f2 - __uint_as_float(ahi[mt][2]));
                ahi[mt][3] = f2tf32(f3); alo[mt][3] = f2tf32(f3 - __uint_as_float(ahi[mt][3]));
            }
            #pragma unroll
            for (int nt = 0; nt < 8; nt++) {
                int nc = wx * 64 + nt * 8 + g;
                unsigned int bh0 = Whi[(k8 + t) * WP + nc];
                unsigned int bh1 = Whi[(k8 + t + 4) * WP + nc];
                unsigned int bl0 = Wlo[(k8 + t) * WP + nc];
                unsigned int bl1 = Wlo[(k8 + t + 4) * WP + nc];
                #pragma unroll
                for (int mt = 0; mt < 2; mt++) {
                    mma_tf32(acc[mt][nt], ahi[mt], bh0, bh1);
                    mma_tf32(acc[mt][nt], alo[mt], bh0, bh1);
                    mma_tf32(acc[mt][nt], ahi[mt], bl0, bl1);
                }
            }
        }
    }

    // epilogue: store h + attention dots via smem combine
    float pS[2][2] = {{0.f, 0.f}, {0.f, 0.f}};
    float pD[2][2] = {{0.f, 0.f}, {0.f, 0.f}};
    #pragma unroll
    for (int nt = 0; nt < 8; nt++) {
        int c = wx * 64 + nt * 8 + t * 2;
        float2 aS = *(const float2*)(asrc + c);
        float2 aD = *(const float2*)(adst + c);
        #pragma unroll
        for (int mt = 0; mt < 2; mt++) {
            int r0 = row0 + wy * 32 + mt * 16 + g, r1 = r0 + 8;
            if (r0 < NN)
                *(float2*)(&g_h[r0 * DIM + c]) = make_float2(acc[mt][nt][0], acc[mt][nt][1]);
            if (r1 < NN)
                *(float2*)(&g_h[r1 * DIM + c]) = make_float2(acc[mt][nt][2], acc[mt][nt][3]);
            pS[mt][0] += acc[mt][nt][0] * aS.x + acc[mt][nt][1] * aS.y;
            pS[mt][1] += acc[mt][nt][2] * aS.x + acc[mt][nt][3] * aS.y;
            pD[mt][0] += acc[mt][nt][0] * aD.x + acc[mt][nt][1] * aD.y;
            pD[mt][1] += acc[mt][nt][2] * aD.x + acc[mt][nt][3] * aD.y;
        }
    }
    #pragma unroll
    for (int o = 1; o <= 2; o <<= 1) {
        #pragma unroll
        for (int mt = 0; mt < 2; mt++) {
            #pragma unroll
            for (int hh = 0; hh < 2; hh++) {
                pS[mt][hh] += __shfl_xor_sync(FULLM, pS[mt][hh], o);
                pD[mt][hh] += __shfl_xor_sync(FULLM, pD[mt][hh], o);
            }
        }
    }
    if (t == 0) {
        #pragma unroll
        for (int mt = 0; mt < 2; mt++) {
            #pragma unroll
            for (int hh = 0; hh < 2; hh++) {
                int lr = wy * 32 + mt * 16 + hh * 8 + g;
                atomicAdd(&sdS[lr], pS[mt][hh]);
                atomicAdd(&sdD[lr], pD[mt][hh]);
            }
        }
    }
    __syncthreads();
    if (tid < 128) {
        int r = row0 + tid;
        if (r < NN) { g_ssrc[r] = sdS[tid]; g_sdst[r] = sdD[tid]; }
    }
}

__device__ __forceinline__ float leaky(float t) { return t > 0.f ? t : NEG * t; }

// ---- fused per-dst softmax + gather-aggregate + bias + relu (+ pool) ----
__global__ __launch_bounds__(256) void gat_agg(const float* __restrict__ bias,
                                               int do_pool,
                                               const int* __restrict__ batch,
                                               const float* __restrict__ Wf,
                                               float* __restrict__ y) {
    int d = (blockIdx.x * blockDim.x + threadIdx.x) >> 5;
    int lane = threadIdx.x & 31;
    if (d >= NN) return;

    int beg = g_rowptr[d], end = g_rowptr[d + 1];
    int deg = end - beg;
    float sdst = g_sdst[d];
    float4 acc = make_float4(0.f, 0.f, 0.f, 0.f);

    if (deg <= 32) {
        // fast path: one gather + one exp per edge; w & s via shuffle
        int s0 = 0;
        float a0 = -CUDART_INF_F;
        if (lane < deg) {
            s0 = g_csrc[beg + lane];
            a0 = leaky(g_ssrc[s0] + sdst);
        }
        float m = a0;
        #pragma unroll
        for (int o = 16; o; o >>= 1) m = fmaxf(m, __shfl_xor_sync(FULLM, m, o));
        float e0 = (lane < deg) ? __expf(a0 - m) : 0.f;
        float sum = e0;
        #pragma unroll
        for (int o = 16; o; o >>= 1) sum += __shfl_xor_sync(FULLM, sum, o);
        float inv = 1.f / (sum + 1e-16f);

        int l = 0;
        for (; l + 1 < deg; l += 2) {
            float w0 = __shfl_sync(FULLM, e0, l) * inv;
            float w1 = __shfl_sync(FULLM, e0, l + 1) * inv;
            int   i0 = __shfl_sync(FULLM, s0, l);
            int   i1 = __shfl_sync(FULLM, s0, l + 1);
            float4 h0 = *(const float4*)(&g_h[i0 * DIM + 4 * lane]);
            float4 h1 = *(const float4*)(&g_h[i1 * DIM + 4 * lane]);
            acc.x += w0 * h0.x + w1 * h1.x;
            acc.y += w0 * h0.y + w1 * h1.y;
            acc.z += w0 * h0.z + w1 * h1.z;
            acc.w += w0 * h0.w + w1 * h1.w;
        }
        if (l < deg) {
            float w0 = __shfl_sync(FULLM, e0, l) * inv;
            int   i0 = __shfl_sync(FULLM, s0, l);
            float4 h0 = *(const float4*)(&g_h[i0 * DIM + 4 * lane]);
            acc.x += w0 * h0.x; acc.y += w0 * h0.y;
            acc.z += w0 * h0.z; acc.w += w0 * h0.w;
        }
    } else {
        // fallback: 3-pass
        float m = -CUDART_INF_F;
        for (int p = beg + lane; p < end; p += 32)
            m = fmaxf(m, leaky(g_ssrc[g_csrc[p]] + sdst));
        #pragma unroll
        for (int o = 16; o; o >>= 1) m = fmaxf(m, __shfl_xor_sync(FULLM, m, o));

        float sum = 0.f;
        for (int p = beg + lane; p < end; p += 32)
            sum += __expf(leaky(g_ssrc[g_csrc[p]] + sdst) - m);
        #pragma unroll
        for (int o = 16; o; o >>= 1) sum += __shfl_xor_sync(FULLM, sum, o);
        float inv = 1.f / (sum + 1e-16f);

        int p = beg;
        for (; p + 1 < end; p += 2) {
            int s0 = g_csrc[p], s1 = g_csrc[p + 1];
            float w0 = __expf(leaky(g_ssrc[s0] + sdst) - m) * inv;
            float w1 = __expf(leaky(g_ssrc[s1] + sdst) - m) * inv;
            float4 h0 = *(const float4*)(&g_h[s0 * DIM + 4 * lane]);
            float4 h1 = *(const float4*)(&g_h[s1 * DIM + 4 * lane]);
            acc.x += w0 * h0.x + w1 * h1.x;
            acc.y += w0 * h0.y + w1 * h1.y;
            acc.z += w0 * h0.z + w1 * h1.z;
            acc.w += w0 * h0.w + w1 * h1.w;
        }
        if (p < end) {
            int s0 = g_csrc[p];
            float w0 = __expf(leaky(g_ssrc[s0] + sdst) - m) * inv;
            float4 h0 = *(const float4*)(&g_h[s0 * DIM + 4 * lane]);
            acc.x += w0 * h0.x; acc.y += w0 * h0.y;
            acc.z += w0 * h0.z; acc.w += w0 * h0.w;
        }
    }

    float4 b4 = *(const float4*)(&bias[4 * lane]);
    acc.x = fmaxf(acc.x + b4.x, 0.f);
    acc.y = fmaxf(acc.y + b4.y, 0.f);
    acc.z = fmaxf(acc.z + b4.z, 0.f);
    acc.w = fmaxf(acc.w + b4.w, 0.f);

    if (do_pool) {
        float4 w4 = *(const float4*)(&Wf[4 * lane]);
        float s = acc.x * w4.x + acc.y * w4.y + acc.z * w4.z + acc.w * w4.w;
        #pragma unroll
        for (int o = 16; o; o >>= 1) s += __shfl_xor_sync(FULLM, s, o);
        if (lane == 0) atomicAdd(&y[batch[d]], s);
    } else {
        *(float4*)(&g_x[d * DIM + 4 * lane]) = acc;
    }
}

__global__ void init_y(const float* __restrict__ bf, float* __restrict__ y) {
    if (threadIdx.x < NG) y[threadIdx.x] = bf[0];
}

extern "C" void kernel_launch(void* const* d_in, const int* in_sizes, int n_in,
                              void* d_out, int out_size) {
    const float* x     = (const float*)d_in[0];
    const int*   ei    = (const int*)  d_in[1];
    const int*   batch = (const int*)  d_in[2];
    const float* Ws    = (const float*)d_in[3];
    const float* asrc  = (const float*)d_in[4];
    const float* adst  = (const float*)d_in[5];
    const float* bias  = (const float*)d_in[6];
    const float* Wf    = (const float*)d_in[7];
    const float* bf    = (const float*)d_in[8];
    float* y = (float*)d_out;

    const int EDGE_BLKS = (ET + 255) / 256;
    const int WARP_BLKS = (NN * 32 + 255) / 256;
    const int GEMM_BLKS = (NN + 127) / 128;

    cudaFuncSetAttribute(gemm_tc, cudaFuncAttributeMaxDynamicSharedMemorySize, GEMM_SMEM);

    zero_deg<<<(NN + 255) / 256, 256>>>();
    count_deg<<<EDGE_BLKS, 256>>>(ei);
    conv_w<<<(NL * DIM * DIM + 255) / 256, 256>>>(Ws);
    scan_local<<<SCAN_B, 1024>>>();
    scan_bsum<<<1, 64>>>();
    scan_addoff<<<SCAN_B, 1024>>>();
    scatter_edges<<<EDGE_BLKS, 256>>>(ei);
    init_y<<<1, 64>>>(bf, y);

    for (int l = 0; l < NL; l++) {
        gemm_tc<<<GEMM_BLKS, 256, GEMM_SMEM>>>(l == 0 ? x : nullptr, l,
                                               asrc + l * DIM, adst + l * DIM);
        gat_agg<<<WARP_BLKS, 256>>>(bias + l * DIM, l == NL - 1 ? 1 : 0, batch, Wf, y);
    }
}

// round 9
// speedup vs baseline: 1.5617x; 1.0792x over previous
#include <cuda_runtime.h>
#include <math_constants.h>
#include <cuda_fp16.h>
#include <cstdint>

#define NN 50000
#define NE 800000
#define ET (NE + NN)
#define DIM 128
#define NL 3
#define NG 64
#define NEG 0.2f
#define SCAN_B ((NN + 1023) / 1024)   // 49
#define FULLM 0xFFFFFFFFu

// ---- scratch ----
__device__ __half g_hh[NN * DIM];    // h in fp16 (gather-only consumer)
__device__ float g_x[NN * DIM];
__device__ float g_ssrc[NN];
__device__ float g_sdst[NN];
__device__ int   g_deg[NN];
__device__ int   g_rowptr[NN + 1];
__device__ int   g_cursor[NN];
__device__ int   g_csrc[ET];
__device__ int   g_bsum[64];
__device__ int   g_boff[64];
__device__ unsigned int g_Whi[NL * DIM * DIM];
__device__ unsigned int g_Wlo[NL * DIM * DIM];

// ================= CSR build =================
__global__ __launch_bounds__(256) void zero_deg() {
    int i = blockIdx.x * blockDim.x + threadIdx.x;
    if (i < NN) g_deg[i] = 0;
}

__global__ __launch_bounds__(256) void count_deg(const int* __restrict__ ei) {
    int e = blockIdx.x * blockDim.x + threadIdx.x;
    if (e >= ET) return;
    int d = (e < NE) ? ei[NE + e] : (e - NE);
    atomicAdd(&g_deg[d], 1);
}

__global__ __launch_bounds__(1024) void scan_local() {
    __shared__ int wsum[32];
    int tid = threadIdx.x, lane = tid & 31, wid = tid >> 5;
    int i = blockIdx.x * 1024 + tid;
    int v = (i < NN) ? g_deg[i] : 0;
    int x = v;
    #pragma unroll
    for (int off = 1; off < 32; off <<= 1) {
        int t = __shfl_up_sync(FULLM, x, off);
        if (lane >= off) x += t;
    }
    if (lane == 31) wsum[wid] = x;
    __syncthreads();
    if (wid == 0) {
        int y = wsum[lane];
        #pragma unroll
        for (int off = 1; off < 32; off <<= 1) {
            int t = __shfl_up_sync(FULLM, y, off);
            if (lane >= off) y += t;
        }
        wsum[lane] = y;
    }
    __syncthreads();
    int incl = x + (wid > 0 ? wsum[wid - 1] : 0);
    if (i < NN) { g_rowptr[i + 1] = incl; g_cursor[i] = incl - v; }
    if (tid == 1023) g_bsum[blockIdx.x] = incl;
}

__global__ __launch_bounds__(64) void scan_bsum() {
    int tid = threadIdx.x, lane = tid & 31, wid = tid >> 5;
    __shared__ int w0sum;
    int v = (tid < SCAN_B) ? g_bsum[tid] : 0;
    int x = v;
    #pragma unroll
    for (int off = 1; off < 32; off <<= 1) {
        int t = __shfl_up_sync(FULLM, x, off);
        if (lane >= off) x += t;
    }
    if (wid == 0 && lane == 31) w0sum = x;
    __syncthreads();
    int incl = x + (wid == 1 ? w0sum : 0);
    if (tid < SCAN_B) g_boff[tid] = incl - v;
}

__global__ __launch_bounds__(1024) void scan_addoff() {
    int i = blockIdx.x * 1024 + threadIdx.x;
    if (i == 0) g_rowptr[0] = 0;
    if (i >= NN) return;
    int off = g_boff[blockIdx.x];
    g_rowptr[i + 1] += off;
    g_cursor[i] += off;
}

__global__ __launch_bounds__(256) void scatter_edges(const int* __restrict__ ei) {
    int e = blockIdx.x * blockDim.x + threadIdx.x;
    if (e >= ET) return;
    int s, d;
    if (e < NE) { s = ei[e]; d = ei[NE + e]; }
    else        { s = d = e - NE; }
    int pos = atomicAdd(&g_cursor[d], 1);
    g_csrc[pos] = s;
}

// ================= W pre-conversion =================
__device__ __forceinline__ unsigned int f2tf32(float f) {
    unsigned int u;
    asm("cvt.rna.tf32.f32 %0, %1;" : "=r"(u) : "f"(f));
    return u;
}

__global__ __launch_bounds__(256) void conv_w(const float* __restrict__ Ws) {
    int i = blockIdx.x * blockDim.x + threadIdx.x;
    if (i >= NL * DIM * DIM) return;
    float w = Ws[i];
    unsigned int hi = f2tf32(w);
    g_Whi[i] = hi;
    g_Wlo[i] = f2tf32(w - __uint_as_float(hi));
}

// ================= TF32x3 GEMM (128x128 block) + fused dots =================
#define WP 136
#define XP 36
#define GEMM_SMEM ((2 * 32 * WP + 128 * XP + 2 * 128) * 4)

__device__ __forceinline__ void mma_tf32(float* d, const unsigned int* a,
                                         unsigned int b0, unsigned int b1) {
    asm volatile("mma.sync.aligned.m16n8k8.row.col.f32.tf32.tf32.f32 "
                 "{%0,%1,%2,%3},{%4,%5,%6,%7},{%8,%9},{%0,%1,%2,%3};"
                 : "+f"(d[0]), "+f"(d[1]), "+f"(d[2]), "+f"(d[3])
                 : "r"(a[0]), "r"(a[1]), "r"(a[2]), "r"(a[3]), "r"(b0), "r"(b1));
}

__global__ __launch_bounds__(256, 2) void gemm_tc(const float* __restrict__ Xin,
                                                  int layer,
                                                  const float* __restrict__ asrc,
                                                  const float* __restrict__ adst) {
    extern __shared__ unsigned int sm[];
    unsigned int* Whi = sm;                     // 32 x WP
    unsigned int* Wlo = sm + 32 * WP;
    float* Xs  = (float*)(sm + 64 * WP);        // 128 x XP
    float* sdS = Xs + 128 * XP;
    float* sdD = sdS + 128;

    const float* X = Xin ? Xin : g_x;
    int tid = threadIdx.x;
    int lane = tid & 31, warp = tid >> 5;
    int wx = warp & 1, wy = warp >> 1;
    int g = lane >> 2, t = lane & 3;
    int row0 = blockIdx.x * 128;

    const uint4* WhiG = (const uint4*)(g_Whi + layer * DIM * DIM);
    const uint4* WloG = (const uint4*)(g_Wlo + layer * DIM * DIM);

    if (tid < 128) { sdS[tid] = 0.f; sdD[tid] = 0.f; }

    float acc[2][8][4];
    #pragma unroll
    for (int mt = 0; mt < 2; mt++)
        #pragma unroll
        for (int nt = 0; nt < 8; nt++)
            #pragma unroll
            for (int i = 0; i < 4; i++) acc[mt][nt][i] = 0.f;

    for (int kc = 0; kc < 4; kc++) {
        __syncthreads();
        #pragma unroll
        for (int i = 0; i < 4; i++) {
            int idx = tid + 256 * i;
            int k = idx >> 5, q = idx & 31;
            int gsrc = (kc * 32 + k) * 32 + q;
            *(uint4*)(&Whi[k * WP + q * 4]) = WhiG[gsrc];
            *(uint4*)(&Wlo[k * WP + q * 4]) = WloG[gsrc];
        }
        #pragma unroll
        for (int i = 0; i < 4; i++) {
            int idx = tid + 256 * i;
            int r = idx >> 3, q = idx & 7;
            int grow = row0 + r;
            float4 v = (grow < NN)
                ? *(const float4*)(&X[grow * DIM + kc * 32 + q * 4])
                : make_float4(0.f, 0.f, 0.f, 0.f);
            *(float4*)(&Xs[r * XP + q * 4]) = v;
        }
        __syncthreads();

        #pragma unroll
        for (int kt = 0; kt < 4; kt++) {
            int k8 = kt * 8;
            unsigned int ahi[2][4], alo[2][4];
            #pragma unroll
            for (int mt = 0; mt < 2; mt++) {
                int lr0 = wy * 32 + mt * 16 + g, lr1 = lr0 + 8;
                float f0 = Xs[lr0 * XP + k8 + t];
                float f1 = Xs[lr1 * XP + k8 + t];
                float f2 = Xs[lr0 * XP + k8 + t + 4];
                float f3 = Xs[lr1 * XP + k8 + t + 4];
                ahi[mt][0] = f2tf32(f0); alo[mt][0] = f2tf32(f0 - __uint_as_float(ahi[mt][0]));
                ahi[mt][1] = f2tf32(f1); alo[mt][1] = f2tf32(f1 - __uint_as_float(ahi[mt][1]));
                ahi[mt][2] = f2tf32(f2); alo[mt][2] = f2tf32(f2 - __uint_as_float(ahi[mt][2]));
                ahi[mt][3] = f2tf32(f3); alo[mt][3] = f2tf32(f3 - __uint_as_float(ahi[mt][3]));
            }
            #pragma unroll
            for (int nt = 0; nt < 8; nt++) {
                int nc = wx * 64 + nt * 8 + g;
                unsigned int bh0 = Whi[(k8 + t) * WP + nc];
                unsigned int bh1 = Whi[(k8 + t + 4) * WP + nc];
                unsigned int bl0 = Wlo[(k8 + t) * WP + nc];
                unsigned int bl1 = Wlo[(k8 + t + 4) * WP + nc];
                #pragma unroll
                for (int mt = 0; mt < 2; mt++) {
                    mma_tf32(acc[mt][nt], ahi[mt], bh0, bh1);
                    mma_tf32(acc[mt][nt], alo[mt], bh0, bh1);
                    mma_tf32(acc[mt][nt], ahi[mt], bl0, bl1);
                }
            }
        }
    }

    // epilogue: store h (fp16) + attention dots via smem combine
    float pS[2][2] = {{0.f, 0.f}, {0.f, 0.f}};
    float pD[2][2] = {{0.f, 0.f}, {0.f, 0.f}};
    #pragma unroll
    for (int nt = 0; nt < 8; nt++) {
        int c = wx * 64 + nt * 8 + t * 2;
        float2 aS = *(const float2*)(asrc + c);
        float2 aD = *(const float2*)(adst + c);
        #pragma unroll
        for (int mt = 0; mt < 2; mt++) {
            int r0 = row0 + wy * 32 + mt * 16 + g, r1 = r0 + 8;
            if (r0 < NN)
                *(__half2*)(&g_hh[r0 * DIM + c]) =
                    __floats2half2_rn(acc[mt][nt][0], acc[mt][nt][1]);
            if (r1 < NN)
                *(__half2*)(&g_hh[r1 * DIM + c]) =
                    __floats2half2_rn(acc[mt][nt][2], acc[mt][nt][3]);
            pS[mt][0] += acc[mt][nt][0] * aS.x + acc[mt][nt][1] * aS.y;
            pS[mt][1] += acc[mt][nt][2] * aS.x + acc[mt][nt][3] * aS.y;
            pD[mt][0] += acc[mt][nt][0] * aD.x + acc[mt][nt][1] * aD.y;
            pD[mt][1] += acc[mt][nt][2] * aD.x + acc[mt][nt][3] * aD.y;
        }
    }
    #pragma unroll
    for (int o = 1; o <= 2; o <<= 1) {
        #pragma unroll
        for (int mt = 0; mt < 2; mt++) {
            #pragma unroll
            for (int hh = 0; hh < 2; hh++) {
                pS[mt][hh] += __shfl_xor_sync(FULLM, pS[mt][hh], o);
                pD[mt][hh] += __shfl_xor_sync(FULLM, pD[mt][hh], o);
            }
        }
    }
    if (t == 0) {
        #pragma unroll
        for (int mt = 0; mt < 2; mt++) {
            #pragma unroll
            for (int hh = 0; hh < 2; hh++) {
                int lr = wy * 32 + mt * 16 + hh * 8 + g;
                atomicAdd(&sdS[lr], pS[mt][hh]);
                atomicAdd(&sdD[lr], pD[mt][hh]);
            }
        }
    }
    __syncthreads();
    if (tid < 128) {
        int r = row0 + tid;
        if (r < NN) { g_ssrc[r] = sdS[tid]; g_sdst[r] = sdD[tid]; }
    }
}

__device__ __forceinline__ float leaky(float t) { return t > 0.f ? t : NEG * t; }

__device__ __forceinline__ void acc_row(float4& acc, float w, int src, int lane) {
    uint2 u = *(const uint2*)(&g_hh[src * DIM + 4 * lane]);
    float2 f01 = __half22float2(*(__half2*)&u.x);
    float2 f23 = __half22float2(*(__half2*)&u.y);
    acc.x += w * f01.x; acc.y += w * f01.y;
    acc.z += w * f23.x; acc.w += w * f23.y;
}

// ---- fused per-dst softmax + gather-aggregate + bias + relu (+ pool) ----
__global__ __launch_bounds__(256) void gat_agg(const float* __restrict__ bias,
                                               int do_pool,
                                               const int* __restrict__ batch,
                                               const float* __restrict__ Wf,
                                               float* __restrict__ y) {
    int d = (blockIdx.x * blockDim.x + threadIdx.x) >> 5;
    int lane = threadIdx.x & 31;
    if (d >= NN) return;

    int beg = g_rowptr[d], end = g_rowptr[d + 1];
    int deg = end - beg;
    float sdst = g_sdst[d];
    float4 acc = make_float4(0.f, 0.f, 0.f, 0.f);

    if (deg <= 32) {
        int s0 = 0;
        float a0 = -CUDART_INF_F;
        if (lane < deg) {
            s0 = g_csrc[beg + lane];
            a0 = leaky(g_ssrc[s0] + sdst);
        }
        float m = a0;
        #pragma unroll
        for (int o = 16; o; o >>= 1) m = fmaxf(m, __shfl_xor_sync(FULLM, m, o));
        float e0 = (lane < deg) ? __expf(a0 - m) : 0.f;
        float sum = e0;
        #pragma unroll
        for (int o = 16; o; o >>= 1) sum += __shfl_xor_sync(FULLM, sum, o);
        float inv = 1.f / (sum + 1e-16f);

        int l = 0;
        for (; l + 1 < deg; l += 2) {
            float w0 = __shfl_sync(FULLM, e0, l) * inv;
            float w1 = __shfl_sync(FULLM, e0, l + 1) * inv;
            int   i0 = __shfl_sync(FULLM, s0, l);
            int   i1 = __shfl_sync(FULLM, s0, l + 1);
            acc_row(acc, w0, i0, lane);
            acc_row(acc, w1, i1, lane);
        }
        if (l < deg) {
            float w0 = __shfl_sync(FULLM, e0, l) * inv;
            int   i0 = __shfl_sync(FULLM, s0, l);
            acc_row(acc, w0, i0, lane);
        }
    } else {
        float m = -CUDART_INF_F;
        for (int p = beg + lane; p < end; p += 32)
            m = fmaxf(m, leaky(g_ssrc[g_csrc[p]] + sdst));
        #pragma unroll
        for (int o = 16; o; o >>= 1) m = fmaxf(m, __shfl_xor_sync(FULLM, m, o));

        float sum = 0.f;
        for (int p = beg + lane; p < end; p += 32)
            sum += __expf(leaky(g_ssrc[g_csrc[p]] + sdst) - m);
        #pragma unroll
        for (int o = 16; o; o >>= 1) sum += __shfl_xor_sync(FULLM, sum, o);
        float inv = 1.f / (sum + 1e-16f);

        for (int p = beg; p < end; p++) {
            int s0 = g_csrc[p];
            float w0 = __expf(leaky(g_ssrc[s0] + sdst) - m) * inv;
            acc_row(acc, w0, s0, lane);
        }
    }

    float4 b4 = *(const float4*)(&bias[4 * lane]);
    acc.x = fmaxf(acc.x + b4.x, 0.f);
    acc.y = fmaxf(acc.y + b4.y, 0.f);
    acc.z = fmaxf(acc.z + b4.z, 0.f);
    acc.w = fmaxf(acc.w + b4.w, 0.f);

    if (do_pool) {
        float4 w4 = *(const float4*)(&Wf[4 * lane]);
        float s = acc.x * w4.x + acc.y * w4.y + acc.z * w4.z + acc.w * w4.w;
        #pragma unroll
        for (int o = 16; o; o >>= 1) s += __shfl_xor_sync(FULLM, s, o);
        if (lane == 0) atomicAdd(&y[batch[d]], s);
    } else {
        *(float4*)(&g_x[d * DIM + 4 * lane]) = acc;
    }
}

__global__ void init_y(const float* __restrict__ bf, float* __restrict__ y) {
    if (threadIdx.x < NG) y[threadIdx.x] = bf[0];
}

extern "C" void kernel_launch(void* const* d_in, const int* in_sizes, int n_in,
                              void* d_out, int out_size) {
    const float* x     = (const float*)d_in[0];
    const int*   ei    = (const int*)  d_in[1];
    const int*   batch = (const int*)  d_in[2];
    const float* Ws    = (const float*)d_in[3];
    const float* asrc  = (const float*)d_in[4];
    const float* adst  = (const float*)d_in[5];
    const float* bias  = (const float*)d_in[6];
    const float* Wf    = (const float*)d_in[7];
    const float* bf    = (const float*)d_in[8];
    float* y = (float*)d_out;

    const int EDGE_BLKS = (ET + 255) / 256;
    const int WARP_BLKS = (NN * 32 + 255) / 256;
    const int GEMM_BLKS = (NN + 127) / 128;

    cudaFuncSetAttribute(gemm_tc, cudaFuncAttributeMaxDynamicSharedMemorySize, GEMM_SMEM);

    zero_deg<<<(NN + 255) / 256, 256>>>();
    count_deg<<<EDGE_BLKS, 256>>>(ei);
    conv_w<<<(NL * DIM * DIM + 255) / 256, 256>>>(Ws);
    scan_local<<<SCAN_B, 1024>>>();
    scan_bsum<<<1, 64>>>();
    scan_addoff<<<SCAN_B, 1024>>>();
    scatter_edges<<<EDGE_BLKS, 256>>>(ei);
    init_y<<<1, 64>>>(bf, y);

    for (int l = 0; l < NL; l++) {
        gemm_tc<<<GEMM_BLKS, 256, GEMM_SMEM>>>(l == 0 ? x : nullptr, l,
                                               asrc + l * DIM, adst + l * DIM);
        gat_agg<<<WARP_BLKS, 256>>>(bias + l * DIM, l == NL - 1 ? 1 : 0, batch, Wf, y);
    }
}